// round 8
// baseline (speedup 1.0000x reference)
#include <cuda_runtime.h>
#include <cuda_fp16.h>
#include <math.h>
#include <stdint.h>

#define BB   8
#define QQ   1024
#define EE   256
#define NHH  8
#define DHH  32
#define STOT 21760
#define MM   (BB*QQ)

// ---------------- scratch (device globals: allocation-free) ----------------
__device__ float g_tmp  [MM*EE];
__device__ float g_tgt1 [MM*EE];
__device__ float g_tgt2 [MM*EE];
__device__ float g_offaw[MM*384];
__device__ float g_bias2[384];

__device__ __half h_value[(size_t)BB*STOT*EE];
__device__ __half h_tgt  [MM*EE];
__device__ __half h_ipw  [768*256];
__device__ __half h_outpw[256*256];
__device__ __half h_offaw[384*256];
__device__ __half h_vpw  [256*256];
__device__ __half h_opw  [256*256];
__device__ __half h_w1   [1024*256];
__device__ __half h_w2   [256*1024];
__device__ __half h_qk   [MM*EE];
__device__ __half h_qk2  [MM*512];
__device__ __half h_v    [MM*EE];
__device__ __half h_ctx  [MM*EE];
__device__ __half h_query[MM*EE];
__device__ __half h_samp [MM*EE];
__device__ __half h_tgt2 [MM*EE];
__device__ __half h_ffn1 [MM*1024];

// ---------------- helpers ----------------
__device__ __forceinline__ void mma_f16(float* c,
                                        uint32_t a0, uint32_t a1, uint32_t a2, uint32_t a3,
                                        uint32_t b0, uint32_t b1) {
    asm volatile("mma.sync.aligned.m16n8k16.row.col.f32.f16.f16.f32 "
                 "{%0,%1,%2,%3}, {%4,%5,%6,%7}, {%8,%9}, {%0,%1,%2,%3};\n"
                 : "+f"(c[0]), "+f"(c[1]), "+f"(c[2]), "+f"(c[3])
                 : "r"(a0), "r"(a1), "r"(a2), "r"(a3), "r"(b0), "r"(b1));
}

__device__ __forceinline__ void ldsm_x4(uint32_t* r, uint32_t addr) {
    asm volatile("ldmatrix.sync.aligned.m8n8.x4.shared.b16 {%0,%1,%2,%3}, [%4];\n"
                 : "=r"(r[0]), "=r"(r[1]), "=r"(r[2]), "=r"(r[3]) : "r"(addr));
}

__device__ __forceinline__ void cp_async16(uint32_t smem_addr, const void* gmem) {
    asm volatile("cp.async.ca.shared.global [%0], [%1], 16;\n" :: "r"(smem_addr), "l"(gmem));
}

__device__ __forceinline__ uint32_t packh2(float a, float b) {
    __half2 h = __floats2half2_rn(a, b);
    return *(uint32_t*)&h;
}

// ---------------- bulk fp32 -> fp16 convert (9 segments) ----------------
struct CvtArgs {
    const float* s[9];
    __half* d[9];
    int n8[9];
};
__global__ void cvt_kernel(CvtArgs a, int total8) {
    int i = blockIdx.x * blockDim.x + threadIdx.x;
    if (i >= total8) return;
    int seg = 0;
#pragma unroll
    for (int k = 0; k < 9; k++) {
        if (i >= a.n8[seg]) { i -= a.n8[seg]; seg++; } else break;
    }
    const float4* sp = (const float4*)a.s[seg] + (size_t)i * 2;
    float4 x = sp[0], y = sp[1];
    uint4 o;
    o.x = packh2(x.x, x.y); o.y = packh2(x.z, x.w);
    o.z = packh2(y.x, y.y); o.w = packh2(y.z, y.w);
    ((uint4*)a.d[seg])[i] = o;
}

__global__ void pack_bias(const float* __restrict__ offb, const float* __restrict__ awb,
                          float* __restrict__ dst) {
    int t = threadIdx.x;
    if (t < 256) dst[t] = offb[t];
    else if (t < 384) dst[t] = awb[t - 256];
}

// ---------------- add (f32 + f32 -> f16) ----------------
__global__ void add_h(const float4* __restrict__ a, const float4* __restrict__ b,
                      __half* __restrict__ c, int n4) {
    int i = blockIdx.x * blockDim.x + threadIdx.x;
    if (i >= n4) return;
    float4 x = a[i], y = b[i];
    uint2 o;
    o.x = packh2(x.x + y.x, x.y + y.y);
    o.y = packh2(x.z + y.z, x.w + y.w);
    ((uint2*)c)[i] = o;
}

// ---------------- fp16 tensor-core GEMM ----------------
#define HSMS 72
#define HSTG (128 * HSMS)
template<int RELU, int WF32, int WF16>
__global__ __launch_bounds__(256, 2)
void gemm_h(const __half* __restrict__ A, const __half* __restrict__ W,
            const float* __restrict__ bias, float* __restrict__ C,
            __half* __restrict__ Ch, int M, int N, int K) {
    extern __shared__ __half smh[];
    const uint32_t base = (uint32_t)__cvta_generic_to_shared(smh);
    uint32_t AsmA[2] = { base,               base + HSTG * 2 };
    uint32_t WsmA[2] = { base + 2*HSTG*2,    base + 3*HSTG*2 };

    const int bm = blockIdx.y * 128;
    const int bn = blockIdx.x * 128;
    const int tid  = threadIdx.x;
    const int warp = tid >> 5;
    const int lane = tid & 31;
    const int wm = warp >> 1;
    const int wn = warp & 1;
    const int lr = lane >> 2;
    const int lc = lane & 3;
    const int l16 = lane & 15;
    const int l4  = lane >> 4;

    uint32_t aOff[2], bOff[4];
#pragma unroll
    for (int mi = 0; mi < 2; mi++)
        aOff[mi] = (wm * 32 + mi * 16 + l16) * (HSMS * 2) + l4 * 16;
#pragma unroll
    for (int p = 0; p < 4; p++)
        bOff[p] = (wn * 64 + p * 16 + l16) * (HSMS * 2) + l4 * 16;

    float acc[2][8][4];
#pragma unroll
    for (int mi = 0; mi < 2; mi++)
#pragma unroll
        for (int ni = 0; ni < 8; ni++)
#pragma unroll
            for (int t = 0; t < 4; t++) acc[mi][ni][t] = 0.f;

    const int lrow = tid >> 1;
    const int lseg = tid & 1;
    const __half* Ag = A + (size_t)(bm + lrow) * K + lseg * 32;
    const __half* Wg = W + (size_t)(bn + lrow) * K + lseg * 32;
    uint32_t aSt[2], wSt[2];
#pragma unroll
    for (int s = 0; s < 2; s++) {
        aSt[s] = AsmA[s] + lrow * (HSMS * 2) + lseg * 64;
        wSt[s] = WsmA[s] + lrow * (HSMS * 2) + lseg * 64;
    }

    const int nch = K >> 6;

#pragma unroll
    for (int j = 0; j < 4; j++) {
        cp_async16(aSt[0] + j * 16, Ag + j * 8);
        cp_async16(wSt[0] + j * 16, Wg + j * 8);
    }
    asm volatile("cp.async.commit_group;\n");

    for (int c = 0; c < nch; c++) {
        const int cur = c & 1;
        if (c + 1 < nch) {
            const __half* Agn = Ag + (size_t)(c + 1) * 64;
            const __half* Wgn = Wg + (size_t)(c + 1) * 64;
            const int nxt = cur ^ 1;
#pragma unroll
            for (int j = 0; j < 4; j++) {
                cp_async16(aSt[nxt] + j * 16, Agn + j * 8);
                cp_async16(wSt[nxt] + j * 16, Wgn + j * 8);
            }
            asm volatile("cp.async.commit_group;\n");
            asm volatile("cp.async.wait_group 1;\n");
        } else {
            asm volatile("cp.async.wait_group 0;\n");
        }
        __syncthreads();

        const uint32_t aS = AsmA[cur];
        const uint32_t wS = WsmA[cur];
#pragma unroll
        for (int kk = 0; kk < 4; kk++) {
            uint32_t a0[4], a1[4];
            ldsm_x4(a0, aS + aOff[0] + kk * 32);
            ldsm_x4(a1, aS + aOff[1] + kk * 32);
#pragma unroll
            for (int p = 0; p < 4; p++) {
                uint32_t bf[4];
                ldsm_x4(bf, wS + bOff[p] + kk * 32);
                mma_f16(acc[0][2*p],   a0[0], a0[1], a0[2], a0[3], bf[0], bf[2]);
                mma_f16(acc[1][2*p],   a1[0], a1[1], a1[2], a1[3], bf[0], bf[2]);
                mma_f16(acc[0][2*p+1], a0[0], a0[1], a0[2], a0[3], bf[1], bf[3]);
                mma_f16(acc[1][2*p+1], a1[0], a1[1], a1[2], a1[3], bf[1], bf[3]);
            }
        }
        __syncthreads();
    }

#pragma unroll
    for (int ni = 0; ni < 8; ni++) {
        int col = bn + wn * 64 + ni * 8 + lc * 2;
        float bj0 = bias[col], bj1 = bias[col + 1];
#pragma unroll
        for (int mi = 0; mi < 2; mi++) {
            int row = bm + wm * 32 + mi * 16 + lr;
            float v0 = acc[mi][ni][0] + bj0;
            float v1 = acc[mi][ni][1] + bj1;
            float v2 = acc[mi][ni][2] + bj0;
            float v3 = acc[mi][ni][3] + bj1;
            if (RELU) {
                v0 = fmaxf(v0, 0.f); v1 = fmaxf(v1, 0.f);
                v2 = fmaxf(v2, 0.f); v3 = fmaxf(v3, 0.f);
            }
            if (WF32) {
                *(float2*)(C + (size_t)row * N + col)       = make_float2(v0, v1);
                *(float2*)(C + (size_t)(row + 8) * N + col) = make_float2(v2, v3);
            }
            if (WF16) {
                *(uint32_t*)(Ch + (size_t)row * N + col)       = packh2(v0, v1);
                *(uint32_t*)(Ch + (size_t)(row + 8) * N + col) = packh2(v2, v3);
            }
        }
    }
}
#define GEMMH_SMEM (4 * HSTG * 2)

// ---------------- fp32-A fused-convert GEMM (value projection, K=256) ------
// A fp32 [M,256] converted to fp16 during staging; W fp16; out fp16.
__global__ __launch_bounds__(256, 2)
void gemm_a32(const float* __restrict__ A, const __half* __restrict__ W,
              const float* __restrict__ bias, __half* __restrict__ Ch,
              int M, int N) {
    constexpr int K = 256;
    constexpr int NCH = 4;
    extern __shared__ __half smh[];
    __half* AbufG[2] = { smh, smh + HSTG };
    const uint32_t base = (uint32_t)__cvta_generic_to_shared(smh);
    uint32_t AsmA[2] = { base,            base + HSTG * 2 };
    uint32_t WsmA[2] = { base + 2*HSTG*2, base + 3*HSTG*2 };

    const int bm = blockIdx.y * 128;
    const int bn = blockIdx.x * 128;
    const int tid  = threadIdx.x;
    const int warp = tid >> 5;
    const int lane = tid & 31;
    const int wm = warp >> 1;
    const int wn = warp & 1;
    const int lr = lane >> 2;
    const int lc = lane & 3;
    const int l16 = lane & 15;
    const int l4  = lane >> 4;

    uint32_t aOff[2], bOff[4];
#pragma unroll
    for (int mi = 0; mi < 2; mi++)
        aOff[mi] = (wm * 32 + mi * 16 + l16) * (HSMS * 2) + l4 * 16;
#pragma unroll
    for (int p = 0; p < 4; p++)
        bOff[p] = (wn * 64 + p * 16 + l16) * (HSMS * 2) + l4 * 16;

    float acc[2][8][4];
#pragma unroll
    for (int mi = 0; mi < 2; mi++)
#pragma unroll
        for (int ni = 0; ni < 8; ni++)
#pragma unroll
            for (int t = 0; t < 4; t++) acc[mi][ni][t] = 0.f;

    const int lrow = tid >> 1;
    const int lseg = tid & 1;
    const float* Ag = A + (size_t)(bm + lrow) * K + lseg * 32;
    const __half* Wg = W + (size_t)(bn + lrow) * K + lseg * 32;
    __half* aDst[2];
#pragma unroll
    for (int s = 0; s < 2; s++)
        aDst[s] = AbufG[s] + lrow * HSMS + lseg * 32;
    uint32_t wSt[2];
#pragma unroll
    for (int s = 0; s < 2; s++)
        wSt[s] = WsmA[s] + lrow * (HSMS * 2) + lseg * 64;

    // prologue: load+convert A chunk 0; cp.async W chunk 0
    uint32_t aPk[16];
    {
        const float4* p = (const float4*)Ag;
#pragma unroll
        for (int j = 0; j < 8; j++) {
            float4 v = p[j];
            aPk[2*j]   = packh2(v.x, v.y);
            aPk[2*j+1] = packh2(v.z, v.w);
        }
    }
#pragma unroll
    for (int j = 0; j < 4; j++) cp_async16(wSt[0] + j * 16, Wg + j * 8);
    asm volatile("cp.async.commit_group;\n");

#pragma unroll
    for (int c = 0; c < NCH; c++) {
        const int cur = c & 1;
        asm volatile("cp.async.wait_group 0;\n");
        // store converted A
        {
            uint4* d = (uint4*)aDst[cur];
#pragma unroll
            for (int j = 0; j < 4; j++)
                d[j] = make_uint4(aPk[4*j], aPk[4*j+1], aPk[4*j+2], aPk[4*j+3]);
        }
        __syncthreads();

        uint32_t aNk[16];
        if (c + 1 < NCH) {
            const int nxt = cur ^ 1;
#pragma unroll
            for (int j = 0; j < 4; j++)
                cp_async16(wSt[nxt] + j * 16, Wg + (size_t)(c + 1) * 64 + j * 8);
            asm volatile("cp.async.commit_group;\n");
            const float4* p = (const float4*)(Ag + (size_t)(c + 1) * 64);
#pragma unroll
            for (int j = 0; j < 8; j++) {
                float4 v = p[j];
                aNk[2*j]   = packh2(v.x, v.y);
                aNk[2*j+1] = packh2(v.z, v.w);
            }
        }

        const uint32_t aS = AsmA[cur];
        const uint32_t wS = WsmA[cur];
#pragma unroll
        for (int kk = 0; kk < 4; kk++) {
            uint32_t a0[4], a1[4];
            ldsm_x4(a0, aS + aOff[0] + kk * 32);
            ldsm_x4(a1, aS + aOff[1] + kk * 32);
#pragma unroll
            for (int p = 0; p < 4; p++) {
                uint32_t bf[4];
                ldsm_x4(bf, wS + bOff[p] + kk * 32);
                mma_f16(acc[0][2*p],   a0[0], a0[1], a0[2], a0[3], bf[0], bf[2]);
                mma_f16(acc[1][2*p],   a1[0], a1[1], a1[2], a1[3], bf[0], bf[2]);
                mma_f16(acc[0][2*p+1], a0[0], a0[1], a0[2], a0[3], bf[1], bf[3]);
                mma_f16(acc[1][2*p+1], a1[0], a1[1], a1[2], a1[3], bf[1], bf[3]);
            }
        }
        __syncthreads();
#pragma unroll
        for (int j = 0; j < 16; j++) aPk[j] = aNk[j];
    }

#pragma unroll
    for (int ni = 0; ni < 8; ni++) {
        int col = bn + wn * 64 + ni * 8 + lc * 2;
        float bj0 = bias[col], bj1 = bias[col + 1];
#pragma unroll
        for (int mi = 0; mi < 2; mi++) {
            int row = bm + wm * 32 + mi * 16 + lr;
            *(uint32_t*)(Ch + (size_t)row * N + col)       = packh2(acc[mi][ni][0] + bj0, acc[mi][ni][1] + bj1);
            *(uint32_t*)(Ch + (size_t)(row + 8) * N + col) = packh2(acc[mi][ni][2] + bj0, acc[mi][ni][3] + bj1);
        }
    }
}

// ---------------- fp16 tensor-core self-attention ----------------
#define AQ_OFF  0
#define AK0_OFF 5120
#define AK1_OFF 7680
#define AV_OFF  10240
#define AP_OFF  12544
#define ATT_SMEM_BYTES ((12544 + 9216) * 2)

__global__ __launch_bounds__(256, 2)
void attn_h(const __half* __restrict__ Qm, int ldq,
            const __half* __restrict__ Km, int ldk,
            const __half* __restrict__ Vm, int ldv,
            __half* __restrict__ Om) {
    extern __shared__ __half sh[];
    const uint32_t shA = (uint32_t)__cvta_generic_to_shared(sh);
    const uint32_t qA  = shA + AQ_OFF * 2;
    uint32_t ksA[2] = { shA + AK0_OFF * 2, shA + AK1_OFF * 2 };
    const uint32_t vtA = shA + AV_OFF * 2;
    const uint32_t pA  = shA + AP_OFF * 2;
    __half* Vts = sh + AV_OFF;
    __half* Ps  = sh + AP_OFF;

    const int bh = blockIdx.y;
    const int b = bh / NHH, h = bh % NHH;
    const int q0 = blockIdx.x * 128;
    const int tid = threadIdx.x;
    const int warp = tid >> 5;
    const int lane = tid & 31;
    const int lr = lane >> 2;
    const int lc = lane & 3;
    const int l16 = lane & 15;
    const int l4  = lane >> 4;
    const int m0 = warp * 16;
    const float scale = 0.17677669529663687f;

    {
        const int lrow = tid >> 1, lseg = tid & 1;
        const __half* qp = Qm + (size_t)(b * QQ + q0 + lrow) * ldq + h * DHH + lseg * 16;
        uint32_t dst = qA + lrow * 80 + lseg * 32;
        cp_async16(dst, qp);
        cp_async16(dst + 16, qp + 8);
    }
    const int krow = tid >> 2;
    const int kseg = tid & 3;
    const __half* kgBase = Km + (size_t)(b * QQ + krow) * ldk + h * DHH + kseg * 8;
    const uint32_t kstOff = krow * 80 + kseg * 16;
    cp_async16(ksA[0] + kstOff, kgBase);
    asm volatile("cp.async.commit_group;\n");

    const int vc = tid & 3;
    const int vr = tid >> 2;
    const int vkc = vc * 8;
    const int vkr = (vr + 8 * vc) & 63;
    const __half* vgBase = Vm + (size_t)(b * QQ + vkr) * ldv + h * DHH + vkc;
    __half* vtDst = Vts + vkc * 72 + vkr;
    uint4 vReg = *(const uint4*)vgBase;

    asm volatile("cp.async.wait_group 0;\n");
    __syncthreads();

    uint32_t qf[2][4];
#pragma unroll
    for (int kb = 0; kb < 2; kb++)
        ldsm_x4(qf[kb], qA + (m0 + l16) * 80 + l4 * 16 + kb * 32);

    {
        const __half* vh = (const __half*)&vReg;
#pragma unroll
        for (int j = 0; j < 8; j++) vtDst[j * 72] = vh[j];
    }
    __syncthreads();

    float acc_o[4][4];
#pragma unroll
    for (int ni = 0; ni < 4; ni++)
#pragma unroll
        for (int t = 0; t < 4; t++) acc_o[ni][t] = 0.f;
    float rs0 = 0.f, rs1 = 0.f;

    const int NT = QQ / 64;
    for (int t = 0; t < NT; t++) {
        const int cur = t & 1;
        const bool more = (t + 1 < NT);
        if (more) {
            cp_async16(ksA[cur ^ 1] + kstOff, kgBase + (size_t)(t + 1) * 64 * ldk);
            asm volatile("cp.async.commit_group;\n");
            vReg = *(const uint4*)(vgBase + (size_t)(t + 1) * 64 * ldv);
        }

        float accs[8][4];
#pragma unroll
        for (int ni = 0; ni < 8; ni++)
#pragma unroll
            for (int tt = 0; tt < 4; tt++) accs[ni][tt] = 0.f;
#pragma unroll
        for (int kb = 0; kb < 2; kb++) {
#pragma unroll
            for (int p = 0; p < 4; p++) {
                uint32_t bf[4];
                ldsm_x4(bf, ksA[cur] + (p * 16 + l16) * 80 + l4 * 16 + kb * 32);
                mma_f16(accs[2*p],   qf[kb][0], qf[kb][1], qf[kb][2], qf[kb][3], bf[0], bf[2]);
                mma_f16(accs[2*p+1], qf[kb][0], qf[kb][1], qf[kb][2], qf[kb][3], bf[1], bf[3]);
            }
        }

#pragma unroll
        for (int ni = 0; ni < 8; ni++) {
            float p0 = __expf(accs[ni][0] * scale);
            float p1 = __expf(accs[ni][1] * scale);
            float p2 = __expf(accs[ni][2] * scale);
            float p3 = __expf(accs[ni][3] * scale);
            rs0 += p0 + p1;
            rs1 += p2 + p3;
            *(uint32_t*)(Ps + (m0 + lr) * 72 + ni * 8 + 2 * lc)     = packh2(p0, p1);
            *(uint32_t*)(Ps + (m0 + 8 + lr) * 72 + ni * 8 + 2 * lc) = packh2(p2, p3);
        }
        __syncwarp();

#pragma unroll
        for (int kb = 0; kb < 4; kb++) {
            uint32_t af[4];
            ldsm_x4(af, pA + (m0 + l16) * 144 + l4 * 16 + kb * 32);
#pragma unroll
            for (int p = 0; p < 2; p++) {
                uint32_t bf[4];
                ldsm_x4(bf, vtA + (p * 16 + l16) * 144 + l4 * 16 + kb * 32);
                mma_f16(acc_o[2*p],   af[0], af[1], af[2], af[3], bf[0], bf[2]);
                mma_f16(acc_o[2*p+1], af[0], af[1], af[2], af[3], bf[1], bf[3]);
            }
        }
        __syncthreads();

        if (more) {
            asm volatile("cp.async.wait_group 0;\n");
            const __half* vh = (const __half*)&vReg;
#pragma unroll
            for (int j = 0; j < 8; j++) vtDst[j * 72] = vh[j];
            __syncthreads();
        }
    }

    rs0 += __shfl_xor_sync(0xffffffff, rs0, 1);
    rs0 += __shfl_xor_sync(0xffffffff, rs0, 2);
    rs1 += __shfl_xor_sync(0xffffffff, rs1, 1);
    rs1 += __shfl_xor_sync(0xffffffff, rs1, 2);
    float inv0 = 1.f / rs0;
    float inv1 = 1.f / rs1;

#pragma unroll
    for (int ni = 0; ni < 4; ni++) {
        int col = h * DHH + ni * 8 + 2 * lc;
        size_t row0 = (size_t)(b * QQ + q0 + m0 + lr) * EE + col;
        size_t row1 = (size_t)(b * QQ + q0 + m0 + 8 + lr) * EE + col;
        *(uint32_t*)(Om + row0) = packh2(acc_o[ni][0] * inv0, acc_o[ni][1] * inv0);
        *(uint32_t*)(Om + row1) = packh2(acc_o[ni][2] * inv1, acc_o[ni][3] * inv1);
    }
}

// ---------------- residual add + LayerNorm (rows of 256) ----------------
// out = LN(X+Y); optional hout = half(out); optional hq = half(out + qpos)
__global__ void addln_kernel(const float* __restrict__ X, const float* __restrict__ Y,
                             const float* __restrict__ gam, const float* __restrict__ bet,
                             float* __restrict__ out, __half* __restrict__ hout,
                             const float* __restrict__ qpos, __half* __restrict__ hq) {
    int row = blockIdx.x;
    int t = threadIdx.x;
    size_t base = (size_t)row * EE;
    float x = X[base + t] + Y[base + t];

    __shared__ float red[8];
    __shared__ float mu_s, rstd_s;

    float s = x;
#pragma unroll
    for (int o = 16; o > 0; o >>= 1) s += __shfl_down_sync(0xffffffff, s, o);
    if ((t & 31) == 0) red[t >> 5] = s;
    __syncthreads();
    if (t == 0) {
        float tot = 0.f;
#pragma unroll
        for (int i = 0; i < 8; i++) tot += red[i];
        mu_s = tot * (1.f / EE);
    }
    __syncthreads();
    float mu = mu_s;
    float d = x - mu;
    float s2 = d * d;
#pragma unroll
    for (int o = 16; o > 0; o >>= 1) s2 += __shfl_down_sync(0xffffffff, s2, o);
    if ((t & 31) == 0) red[t >> 5] = s2;
    __syncthreads();
    if (t == 0) {
        float tot = 0.f;
#pragma unroll
        for (int i = 0; i < 8; i++) tot += red[i];
        rstd_s = rsqrtf(tot * (1.f / EE) + 1e-5f);
    }
    __syncthreads();
    float val = (x - mu) * rstd_s * gam[t] + bet[t];
    out[base + t] = val;
    if (hout) hout[base + t] = __float2half_rn(val);
    if (hq)   hq[base + t]   = __float2half_rn(val + qpos[base + t]);
}

// ---------------- attention-weight softmax over 16 (stride-384 rows) -------
__global__ void awsm_kernel(float* __restrict__ offaw) {
    int i = blockIdx.x * blockDim.x + threadIdx.x;
    if (i >= BB * QQ * NHH) return;
    float* p = offaw + (size_t)(i >> 3) * 384 + 256 + (i & 7) * 16;
    float v[16];
    float m = -1e30f;
#pragma unroll
    for (int j = 0; j < 16; j++) { v[j] = p[j]; m = fmaxf(m, v[j]); }
    float s = 0.f;
#pragma unroll
    for (int j = 0; j < 16; j++) { v[j] = __expf(v[j] - m); s += v[j]; }
    float inv = 1.f / s;
#pragma unroll
    for (int j = 0; j < 16; j++) p[j] = v[j] * inv;
}

// ---------------- deformable bilinear sampling (fp16 value) ----------------
__device__ __forceinline__ float fetch_corner_h(const __half* __restrict__ vb,
                                                float yi, float xi, int Hl, int Wl) {
    bool valid = (xi >= 0.f) && (xi <= (float)(Wl - 1)) &&
                 (yi >= 0.f) && (yi <= (float)(Hl - 1));
    int xc = (int)fminf(fmaxf(xi, 0.f), (float)(Wl - 1));
    int yc = (int)fminf(fmaxf(yi, 0.f), (float)(Hl - 1));
    float v = __half2float(vb[(size_t)(yc * Wl + xc) * EE]);
    return valid ? v : 0.f;
}

__global__ void sample_kernel(const float* __restrict__ refp, const float* __restrict__ offaw,
                              const __half* __restrict__ val, __half* __restrict__ out) {
    int wg = (blockIdx.x * blockDim.x + threadIdx.x) >> 5;
    int lane = threadIdx.x & 31;
    if (wg >= BB * QQ * NHH) return;
    int h = wg % NHH;
    int bq = wg / NHH;
    int b = bq / QQ;

    const float* rp = refp + (size_t)bq * 8;
    const float* op = offaw + (size_t)bq * 384 + h * 32;
    const float* ap = offaw + (size_t)bq * 384 + 256 + h * 16;

    const int Hs[4] = {128, 64, 32, 16};
    const int S0[4] = {0, 16384, 20480, 21504};

    float acc = 0.f;
#pragma unroll
    for (int l = 0; l < 4; l++) {
        int Hi = Hs[l], Wi = Hs[l];
        float Hl = (float)Hi, Wl = (float)Wi;
        const __half* vb = val + ((size_t)b * STOT + S0[l]) * EE + h * 32 + lane;
        float rx = rp[l * 2 + 0], ry = rp[l * 2 + 1];
#pragma unroll
        for (int p = 0; p < 4; p++) {
            float ox = op[l * 8 + p * 2 + 0];
            float oy = op[l * 8 + p * 2 + 1];
            float a = ap[l * 4 + p];
            float x = fmaf(rx, Wl, ox) - 0.5f;
            float y = fmaf(ry, Hl, oy) - 0.5f;
            float x0 = floorf(x), y0 = floorf(y);
            float wx = x - x0, wy = y - y0;
            float sum = 0.f;
            sum += fetch_corner_h(vb, y0,       x0,       Hi, Wi) * (1.f - wy) * (1.f - wx);
            sum += fetch_corner_h(vb, y0,       x0 + 1.f, Hi, Wi) * (1.f - wy) * wx;
            sum += fetch_corner_h(vb, y0 + 1.f, x0,       Hi, Wi) * wy * (1.f - wx);
            sum += fetch_corner_h(vb, y0 + 1.f, x0 + 1.f, Hi, Wi) * wy * wx;
            acc = fmaf(a, sum, acc);
        }
    }
    out[(size_t)bq * EE + h * 32 + lane] = __float2half_rn(acc);
}

// ---------------- launch ----------------
extern "C" void kernel_launch(void* const* d_in, const int* in_sizes, int n_in,
                              void* d_out, int out_size) {
    const float* tgt   = (const float*)d_in[0];
    const float* qpos  = (const float*)d_in[1];
    const float* refp  = (const float*)d_in[2];
    const float* src   = (const float*)d_in[3];
    const float* ipw   = (const float*)d_in[6];
    const float* ipb   = (const float*)d_in[7];
    const float* outpw = (const float*)d_in[8];
    const float* outpb = (const float*)d_in[9];
    const float* n1g   = (const float*)d_in[10];
    const float* n1b   = (const float*)d_in[11];
    const float* offw  = (const float*)d_in[12];
    const float* offb  = (const float*)d_in[13];
    const float* aww   = (const float*)d_in[14];
    const float* awb   = (const float*)d_in[15];
    const float* vpw   = (const float*)d_in[16];
    const float* vpb   = (const float*)d_in[17];
    const float* opw   = (const float*)d_in[18];
    const float* opb   = (const float*)d_in[19];
    const float* n2g   = (const float*)d_in[20];
    const float* n2b   = (const float*)d_in[21];
    const float* w1    = (const float*)d_in[22];
    const float* b1    = (const float*)d_in[23];
    const float* w2    = (const float*)d_in[24];
    const float* b2    = (const float*)d_in[25];
    const float* n3g   = (const float*)d_in[26];
    const float* n3b   = (const float*)d_in[27];
    float* out = (float*)d_out;

    float *tmp, *tgt1, *tgt2, *offaw, *bias2;
    cudaGetSymbolAddress((void**)&tmp,   g_tmp);
    cudaGetSymbolAddress((void**)&tgt1,  g_tgt1);
    cudaGetSymbolAddress((void**)&tgt2,  g_tgt2);
    cudaGetSymbolAddress((void**)&offaw, g_offaw);
    cudaGetSymbolAddress((void**)&bias2, g_bias2);

    __half *hval, *htgt, *hipw, *houtpw, *hoffaw, *hvpw, *hopw, *hw1, *hw2;
    __half *hqk, *hqk2, *hv, *hctx, *hquery, *hsamp, *htgt2, *hffn1;
    cudaGetSymbolAddress((void**)&hval,   h_value);
    cudaGetSymbolAddress((void**)&htgt,   h_tgt);
    cudaGetSymbolAddress((void**)&hipw,   h_ipw);
    cudaGetSymbolAddress((void**)&houtpw, h_outpw);
    cudaGetSymbolAddress((void**)&hoffaw, h_offaw);
    cudaGetSymbolAddress((void**)&hvpw,   h_vpw);
    cudaGetSymbolAddress((void**)&hopw,   h_opw);
    cudaGetSymbolAddress((void**)&hw1,    h_w1);
    cudaGetSymbolAddress((void**)&hw2,    h_w2);
    cudaGetSymbolAddress((void**)&hqk,    h_qk);
    cudaGetSymbolAddress((void**)&hqk2,   h_qk2);
    cudaGetSymbolAddress((void**)&hv,     h_v);
    cudaGetSymbolAddress((void**)&hctx,   h_ctx);
    cudaGetSymbolAddress((void**)&hquery, h_query);
    cudaGetSymbolAddress((void**)&hsamp,  h_samp);
    cudaGetSymbolAddress((void**)&htgt2,  h_tgt2);
    cudaGetSymbolAddress((void**)&hffn1,  h_ffn1);

    cudaFuncSetAttribute(gemm_h<0,0,1>, cudaFuncAttributeMaxDynamicSharedMemorySize, GEMMH_SMEM);
    cudaFuncSetAttribute(gemm_h<0,1,0>, cudaFuncAttributeMaxDynamicSharedMemorySize, GEMMH_SMEM);
    cudaFuncSetAttribute(gemm_h<1,0,1>, cudaFuncAttributeMaxDynamicSharedMemorySize, GEMMH_SMEM);
    cudaFuncSetAttribute(gemm_a32,      cudaFuncAttributeMaxDynamicSharedMemorySize, GEMMH_SMEM);
    cudaFuncSetAttribute(attn_h, cudaFuncAttributeMaxDynamicSharedMemorySize, ATT_SMEM_BYTES);

    // 0) convert inputs/weights to fp16 (src handled inside gemm_a32)
    CvtArgs ca;
    const float* ss[9] = { tgt, ipw, outpw, offw, aww, vpw, opw, w1, w2 };
    __half* dd[9] = { htgt, hipw, houtpw, hoffaw, hoffaw + 256*256, hvpw, hopw, hw1, hw2 };
    int nn[9] = { MM*EE/8, 768*256/8, 65536/8, 65536/8, 32768/8, 65536/8, 65536/8, 262144/8, 262144/8 };
    int total8 = 0;
    for (int i = 0; i < 9; i++) { ca.s[i] = ss[i]; ca.d[i] = dd[i]; ca.n8[i] = nn[i]; total8 += nn[i]; }
    cvt_kernel<<<(total8 + 255) / 256, 256>>>(ca, total8);
    pack_bias<<<1, 384>>>(offb, awb, bias2);

    const int M = MM;
    const int n4 = M * EE / 4;

    // 1) qk = tgt + query_pos (fp16)
    add_h<<<(n4 + 255) / 256, 256>>>((const float4*)tgt, (const float4*)qpos, hqk, n4);

    // 2) q|k merged projection + v projection
    gemm_h<0,0,1><<<dim3(4, M/128), 256, GEMMH_SMEM>>>(hqk, hipw,           ipb,     nullptr, hqk2, M, 512, 256);
    gemm_h<0,0,1><<<dim3(2, M/128), 256, GEMMH_SMEM>>>(htgt, hipw + 512*256, ipb+512, nullptr, hv,   M, 256, 256);

    // 3) self-attention
    attn_h<<<dim3(QQ/128, BB*NHH), 256, ATT_SMEM_BYTES>>>(hqk2, 512, hqk2 + 256, 512, hv, 256, hctx);

    // 4) out projection + LN1 (fused query = LN1 + qpos, fp16)
    gemm_h<0,1,0><<<dim3(2, M/128), 256, GEMMH_SMEM>>>(hctx, houtpw, outpb, tmp, nullptr, M, 256, 256);
    addln_kernel<<<M, 256>>>(tgt, tmp, n1g, n1b, tgt1, nullptr, qpos, hquery);

    // 5) value projection with fused fp32->fp16 A conversion, fp16 output
    gemm_a32<<<dim3(2, (BB*STOT)/128), 256, GEMMH_SMEM>>>(src, hvpw, vpb, hval, BB*STOT, 256);

    // 6) merged offsets|attention-weights projection (N=384)
    gemm_h<0,1,0><<<dim3(3, M/128), 256, GEMMH_SMEM>>>(hquery, hoffaw, bias2, offaw, nullptr, M, 384, 256);
    awsm_kernel<<<(BB*QQ*NHH + 255) / 256, 256>>>(offaw);

    // 7) deformable sampling (fp16 value, fp16 out)
    sample_kernel<<<(BB*QQ*NHH) / 8, 256>>>(refp, offaw, hval, hsamp);

    // 8) output projection + LN2
    gemm_h<0,1,0><<<dim3(2, M/128), 256, GEMMH_SMEM>>>(hsamp, hopw, opb, tmp, nullptr, M, 256, 256);
    addln_kernel<<<M, 256>>>(tgt1, tmp, n2g, n2b, tgt2, htgt2, nullptr, nullptr);

    // 9) FFN + LN3
    gemm_h<1,0,1><<<dim3(8, M/128), 256, GEMMH_SMEM>>>(htgt2, hw1, b1, nullptr, hffn1, M, 1024, 256);
    gemm_h<0,1,0><<<dim3(2, M/128), 256, GEMMH_SMEM>>>(hffn1, hw2, b2, tmp, nullptr, M, 256, 1024);
    addln_kernel<<<M, 256>>>(tgt2, tmp, n3g, n3b, out, nullptr, nullptr, nullptr);
}

// round 9
// speedup vs baseline: 1.0338x; 1.0338x over previous
#include <cuda_runtime.h>
#include <cuda_fp16.h>
#include <math.h>
#include <stdint.h>

#define BB   8
#define QQ   1024
#define EE   256
#define NHH  8
#define DHH  32
#define STOT 21760
#define MM   (BB*QQ)

// ---------------- scratch (device globals: allocation-free) ----------------
__device__ float g_tmp  [MM*EE];
__device__ float g_tgt1 [MM*EE];
__device__ float g_tgt2 [MM*EE];
__device__ float g_offaw[MM*384];
__device__ float g_bias2[384];

__device__ __half h_value[(size_t)BB*STOT*EE];
__device__ __half h_src  [(size_t)BB*STOT*EE];
__device__ __half h_tgt  [MM*EE];
__device__ __half h_ipw  [768*256];
__device__ __half h_outpw[256*256];
__device__ __half h_offaw[384*256];
__device__ __half h_vpw  [256*256];
__device__ __half h_opw  [256*256];
__device__ __half h_w1   [1024*256];
__device__ __half h_w2   [256*1024];
__device__ __half h_qk   [MM*EE];
__device__ __half h_qk2  [MM*512];
__device__ __half h_v    [MM*EE];
__device__ __half h_ctx  [MM*EE];
__device__ __half h_query[MM*EE];
__device__ __half h_samp [MM*EE];
__device__ __half h_tgt2 [MM*EE];
__device__ __half h_ffn1 [MM*1024];

// ---------------- helpers ----------------
__device__ __forceinline__ void mma_f16(float* c,
                                        uint32_t a0, uint32_t a1, uint32_t a2, uint32_t a3,
                                        uint32_t b0, uint32_t b1) {
    asm volatile("mma.sync.aligned.m16n8k16.row.col.f32.f16.f16.f32 "
                 "{%0,%1,%2,%3}, {%4,%5,%6,%7}, {%8,%9}, {%0,%1,%2,%3};\n"
                 : "+f"(c[0]), "+f"(c[1]), "+f"(c[2]), "+f"(c[3])
                 : "r"(a0), "r"(a1), "r"(a2), "r"(a3), "r"(b0), "r"(b1));
}

__device__ __forceinline__ void ldsm_x4(uint32_t* r, uint32_t addr) {
    asm volatile("ldmatrix.sync.aligned.m8n8.x4.shared.b16 {%0,%1,%2,%3}, [%4];\n"
                 : "=r"(r[0]), "=r"(r[1]), "=r"(r[2]), "=r"(r[3]) : "r"(addr));
}

__device__ __forceinline__ void cp_async16(uint32_t smem_addr, const void* gmem) {
    asm volatile("cp.async.ca.shared.global [%0], [%1], 16;\n" :: "r"(smem_addr), "l"(gmem));
}

__device__ __forceinline__ uint32_t packh2(float a, float b) {
    __half2 h = __floats2half2_rn(a, b);
    return *(uint32_t*)&h;
}

// ---------------- bulk fp32 -> fp16 convert (10 segments) ----------------
struct CvtArgs {
    const float* s[10];
    __half* d[10];
    int n8[10];
};
__global__ void cvt_kernel(CvtArgs a, int total8) {
    int i = blockIdx.x * blockDim.x + threadIdx.x;
    if (i >= total8) return;
    int seg = 0;
#pragma unroll
    for (int k = 0; k < 10; k++) {
        if (i >= a.n8[seg]) { i -= a.n8[seg]; seg++; } else break;
    }
    const float4* sp = (const float4*)a.s[seg] + (size_t)i * 2;
    float4 x = sp[0], y = sp[1];
    uint4 o;
    o.x = packh2(x.x, x.y); o.y = packh2(x.z, x.w);
    o.z = packh2(y.x, y.y); o.w = packh2(y.z, y.w);
    ((uint4*)a.d[seg])[i] = o;
}

__global__ void pack_bias(const float* __restrict__ offb, const float* __restrict__ awb,
                          float* __restrict__ dst) {
    int t = threadIdx.x;
    if (t < 256) dst[t] = offb[t];
    else if (t < 384) dst[t] = awb[t - 256];
}

// ---------------- add (f32 + f32 -> f16) ----------------
__global__ void add_h(const float4* __restrict__ a, const float4* __restrict__ b,
                      __half* __restrict__ c, int n4) {
    int i = blockIdx.x * blockDim.x + threadIdx.x;
    if (i >= n4) return;
    float4 x = a[i], y = b[i];
    uint2 o;
    o.x = packh2(x.x + y.x, x.y + y.y);
    o.y = packh2(x.z + y.z, x.w + y.w);
    ((uint2*)c)[i] = o;
}

// ---------------- fp16 tensor-core GEMM ----------------
#define HSMS 72
#define HSTG (128 * HSMS)
template<int RELU, int WF32, int WF16>
__global__ __launch_bounds__(256, 2)
void gemm_h(const __half* __restrict__ A, const __half* __restrict__ W,
            const float* __restrict__ bias, float* __restrict__ C,
            __half* __restrict__ Ch, int M, int N, int K) {
    extern __shared__ __half smh[];
    const uint32_t base = (uint32_t)__cvta_generic_to_shared(smh);
    uint32_t AsmA[2] = { base,               base + HSTG * 2 };
    uint32_t WsmA[2] = { base + 2*HSTG*2,    base + 3*HSTG*2 };

    const int bm = blockIdx.y * 128;
    const int bn = blockIdx.x * 128;
    const int tid  = threadIdx.x;
    const int warp = tid >> 5;
    const int lane = tid & 31;
    const int wm = warp >> 1;
    const int wn = warp & 1;
    const int lr = lane >> 2;
    const int lc = lane & 3;
    const int l16 = lane & 15;
    const int l4  = lane >> 4;

    uint32_t aOff[2], bOff[4];
#pragma unroll
    for (int mi = 0; mi < 2; mi++)
        aOff[mi] = (wm * 32 + mi * 16 + l16) * (HSMS * 2) + l4 * 16;
#pragma unroll
    for (int p = 0; p < 4; p++)
        bOff[p] = (wn * 64 + p * 16 + l16) * (HSMS * 2) + l4 * 16;

    float acc[2][8][4];
#pragma unroll
    for (int mi = 0; mi < 2; mi++)
#pragma unroll
        for (int ni = 0; ni < 8; ni++)
#pragma unroll
            for (int t = 0; t < 4; t++) acc[mi][ni][t] = 0.f;

    const int lrow = tid >> 1;
    const int lseg = tid & 1;
    const __half* Ag = A + (size_t)(bm + lrow) * K + lseg * 32;
    const __half* Wg = W + (size_t)(bn + lrow) * K + lseg * 32;
    uint32_t aSt[2], wSt[2];
#pragma unroll
    for (int s = 0; s < 2; s++) {
        aSt[s] = AsmA[s] + lrow * (HSMS * 2) + lseg * 64;
        wSt[s] = WsmA[s] + lrow * (HSMS * 2) + lseg * 64;
    }

    const int nch = K >> 6;

#pragma unroll
    for (int j = 0; j < 4; j++) {
        cp_async16(aSt[0] + j * 16, Ag + j * 8);
        cp_async16(wSt[0] + j * 16, Wg + j * 8);
    }
    asm volatile("cp.async.commit_group;\n");

    for (int c = 0; c < nch; c++) {
        const int cur = c & 1;
        if (c + 1 < nch) {
            const __half* Agn = Ag + (size_t)(c + 1) * 64;
            const __half* Wgn = Wg + (size_t)(c + 1) * 64;
            const int nxt = cur ^ 1;
#pragma unroll
            for (int j = 0; j < 4; j++) {
                cp_async16(aSt[nxt] + j * 16, Agn + j * 8);
                cp_async16(wSt[nxt] + j * 16, Wgn + j * 8);
            }
            asm volatile("cp.async.commit_group;\n");
            asm volatile("cp.async.wait_group 1;\n");
        } else {
            asm volatile("cp.async.wait_group 0;\n");
        }
        __syncthreads();

        const uint32_t aS = AsmA[cur];
        const uint32_t wS = WsmA[cur];
#pragma unroll
        for (int kk = 0; kk < 4; kk++) {
            uint32_t a0[4], a1[4];
            ldsm_x4(a0, aS + aOff[0] + kk * 32);
            ldsm_x4(a1, aS + aOff[1] + kk * 32);
#pragma unroll
            for (int p = 0; p < 4; p++) {
                uint32_t bf[4];
                ldsm_x4(bf, wS + bOff[p] + kk * 32);
                mma_f16(acc[0][2*p],   a0[0], a0[1], a0[2], a0[3], bf[0], bf[2]);
                mma_f16(acc[1][2*p],   a1[0], a1[1], a1[2], a1[3], bf[0], bf[2]);
                mma_f16(acc[0][2*p+1], a0[0], a0[1], a0[2], a0[3], bf[1], bf[3]);
                mma_f16(acc[1][2*p+1], a1[0], a1[1], a1[2], a1[3], bf[1], bf[3]);
            }
        }
        __syncthreads();
    }

#pragma unroll
    for (int ni = 0; ni < 8; ni++) {
        int col = bn + wn * 64 + ni * 8 + lc * 2;
        float bj0 = bias[col], bj1 = bias[col + 1];
#pragma unroll
        for (int mi = 0; mi < 2; mi++) {
            int row = bm + wm * 32 + mi * 16 + lr;
            float v0 = acc[mi][ni][0] + bj0;
            float v1 = acc[mi][ni][1] + bj1;
            float v2 = acc[mi][ni][2] + bj0;
            float v3 = acc[mi][ni][3] + bj1;
            if (RELU) {
                v0 = fmaxf(v0, 0.f); v1 = fmaxf(v1, 0.f);
                v2 = fmaxf(v2, 0.f); v3 = fmaxf(v3, 0.f);
            }
            if (WF32) {
                *(float2*)(C + (size_t)row * N + col)       = make_float2(v0, v1);
                *(float2*)(C + (size_t)(row + 8) * N + col) = make_float2(v2, v3);
            }
            if (WF16) {
                *(uint32_t*)(Ch + (size_t)row * N + col)       = packh2(v0, v1);
                *(uint32_t*)(Ch + (size_t)(row + 8) * N + col) = packh2(v2, v3);
            }
        }
    }
}
#define GEMMH_SMEM (4 * HSTG * 2)

// ---------------- fp16 tensor-core self-attention ----------------
#define AQ_OFF  0
#define AK0_OFF 5120
#define AK1_OFF 7680
#define AV_OFF  10240
#define AP_OFF  12544
#define ATT_SMEM_BYTES ((12544 + 9216) * 2)

__global__ __launch_bounds__(256, 2)
void attn_h(const __half* __restrict__ Qm, int ldq,
            const __half* __restrict__ Km, int ldk,
            const __half* __restrict__ Vm, int ldv,
            __half* __restrict__ Om) {
    extern __shared__ __half sh[];
    const uint32_t shA = (uint32_t)__cvta_generic_to_shared(sh);
    const uint32_t qA  = shA + AQ_OFF * 2;
    uint32_t ksA[2] = { shA + AK0_OFF * 2, shA + AK1_OFF * 2 };
    const uint32_t vtA = shA + AV_OFF * 2;
    const uint32_t pA  = shA + AP_OFF * 2;
    __half* Vts = sh + AV_OFF;
    __half* Ps  = sh + AP_OFF;

    const int bh = blockIdx.y;
    const int b = bh / NHH, h = bh % NHH;
    const int q0 = blockIdx.x * 128;
    const int tid = threadIdx.x;
    const int warp = tid >> 5;
    const int lane = tid & 31;
    const int lr = lane >> 2;
    const int lc = lane & 3;
    const int l16 = lane & 15;
    const int l4  = lane >> 4;
    const int m0 = warp * 16;
    const float scale = 0.17677669529663687f;

    {
        const int lrow = tid >> 1, lseg = tid & 1;
        const __half* qp = Qm + (size_t)(b * QQ + q0 + lrow) * ldq + h * DHH + lseg * 16;
        uint32_t dst = qA + lrow * 80 + lseg * 32;
        cp_async16(dst, qp);
        cp_async16(dst + 16, qp + 8);
    }
    const int krow = tid >> 2;
    const int kseg = tid & 3;
    const __half* kgBase = Km + (size_t)(b * QQ + krow) * ldk + h * DHH + kseg * 8;
    const uint32_t kstOff = krow * 80 + kseg * 16;
    cp_async16(ksA[0] + kstOff, kgBase);
    asm volatile("cp.async.commit_group;\n");

    const int vc = tid & 3;
    const int vr = tid >> 2;
    const int vkc = vc * 8;
    const int vkr = (vr + 8 * vc) & 63;
    const __half* vgBase = Vm + (size_t)(b * QQ + vkr) * ldv + h * DHH + vkc;
    __half* vtDst = Vts + vkc * 72 + vkr;
    uint4 vReg = *(const uint4*)vgBase;

    asm volatile("cp.async.wait_group 0;\n");
    __syncthreads();

    uint32_t qf[2][4];
#pragma unroll
    for (int kb = 0; kb < 2; kb++)
        ldsm_x4(qf[kb], qA + (m0 + l16) * 80 + l4 * 16 + kb * 32);

    {
        const __half* vh = (const __half*)&vReg;
#pragma unroll
        for (int j = 0; j < 8; j++) vtDst[j * 72] = vh[j];
    }
    __syncthreads();

    float acc_o[4][4];
#pragma unroll
    for (int ni = 0; ni < 4; ni++)
#pragma unroll
        for (int t = 0; t < 4; t++) acc_o[ni][t] = 0.f;
    float rs0 = 0.f, rs1 = 0.f;

    const int NT = QQ / 64;
    for (int t = 0; t < NT; t++) {
        const int cur = t & 1;
        const bool more = (t + 1 < NT);
        if (more) {
            cp_async16(ksA[cur ^ 1] + kstOff, kgBase + (size_t)(t + 1) * 64 * ldk);
            asm volatile("cp.async.commit_group;\n");
            vReg = *(const uint4*)(vgBase + (size_t)(t + 1) * 64 * ldv);
        }

        float accs[8][4];
#pragma unroll
        for (int ni = 0; ni < 8; ni++)
#pragma unroll
            for (int tt = 0; tt < 4; tt++) accs[ni][tt] = 0.f;
#pragma unroll
        for (int kb = 0; kb < 2; kb++) {
#pragma unroll
            for (int p = 0; p < 4; p++) {
                uint32_t bf[4];
                ldsm_x4(bf, ksA[cur] + (p * 16 + l16) * 80 + l4 * 16 + kb * 32);
                mma_f16(accs[2*p],   qf[kb][0], qf[kb][1], qf[kb][2], qf[kb][3], bf[0], bf[2]);
                mma_f16(accs[2*p+1], qf[kb][0], qf[kb][1], qf[kb][2], qf[kb][3], bf[1], bf[3]);
            }
        }

#pragma unroll
        for (int ni = 0; ni < 8; ni++) {
            float p0 = __expf(accs[ni][0] * scale);
            float p1 = __expf(accs[ni][1] * scale);
            float p2 = __expf(accs[ni][2] * scale);
            float p3 = __expf(accs[ni][3] * scale);
            rs0 += p0 + p1;
            rs1 += p2 + p3;
            *(uint32_t*)(Ps + (m0 + lr) * 72 + ni * 8 + 2 * lc)     = packh2(p0, p1);
            *(uint32_t*)(Ps + (m0 + 8 + lr) * 72 + ni * 8 + 2 * lc) = packh2(p2, p3);
        }
        __syncwarp();

#pragma unroll
        for (int kb = 0; kb < 4; kb++) {
            uint32_t af[4];
            ldsm_x4(af, pA + (m0 + l16) * 144 + l4 * 16 + kb * 32);
#pragma unroll
            for (int p = 0; p < 2; p++) {
                uint32_t bf[4];
                ldsm_x4(bf, vtA + (p * 16 + l16) * 144 + l4 * 16 + kb * 32);
                mma_f16(acc_o[2*p],   af[0], af[1], af[2], af[3], bf[0], bf[2]);
                mma_f16(acc_o[2*p+1], af[0], af[1], af[2], af[3], bf[1], bf[3]);
            }
        }
        __syncthreads();

        if (more) {
            asm volatile("cp.async.wait_group 0;\n");
            const __half* vh = (const __half*)&vReg;
#pragma unroll
            for (int j = 0; j < 8; j++) vtDst[j * 72] = vh[j];
            __syncthreads();
        }
    }

    rs0 += __shfl_xor_sync(0xffffffff, rs0, 1);
    rs0 += __shfl_xor_sync(0xffffffff, rs0, 2);
    rs1 += __shfl_xor_sync(0xffffffff, rs1, 1);
    rs1 += __shfl_xor_sync(0xffffffff, rs1, 2);
    float inv0 = 1.f / rs0;
    float inv1 = 1.f / rs1;

#pragma unroll
    for (int ni = 0; ni < 4; ni++) {
        int col = h * DHH + ni * 8 + 2 * lc;
        size_t row0 = (size_t)(b * QQ + q0 + m0 + lr) * EE + col;
        size_t row1 = (size_t)(b * QQ + q0 + m0 + 8 + lr) * EE + col;
        *(uint32_t*)(Om + row0) = packh2(acc_o[ni][0] * inv0, acc_o[ni][1] * inv0);
        *(uint32_t*)(Om + row1) = packh2(acc_o[ni][2] * inv1, acc_o[ni][3] * inv1);
    }
}

// ---------------- residual add + LayerNorm (rows of 256) ----------------
__global__ void addln_kernel(const float* __restrict__ X, const float* __restrict__ Y,
                             const float* __restrict__ gam, const float* __restrict__ bet,
                             float* __restrict__ out, __half* __restrict__ hout,
                             const float* __restrict__ qpos, __half* __restrict__ hq) {
    int row = blockIdx.x;
    int t = threadIdx.x;
    size_t base = (size_t)row * EE;
    float x = X[base + t] + Y[base + t];

    __shared__ float red[8];
    __shared__ float mu_s, rstd_s;

    float s = x;
#pragma unroll
    for (int o = 16; o > 0; o >>= 1) s += __shfl_down_sync(0xffffffff, s, o);
    if ((t & 31) == 0) red[t >> 5] = s;
    __syncthreads();
    if (t == 0) {
        float tot = 0.f;
#pragma unroll
        for (int i = 0; i < 8; i++) tot += red[i];
        mu_s = tot * (1.f / EE);
    }
    __syncthreads();
    float mu = mu_s;
    float d = x - mu;
    float s2 = d * d;
#pragma unroll
    for (int o = 16; o > 0; o >>= 1) s2 += __shfl_down_sync(0xffffffff, s2, o);
    if ((t & 31) == 0) red[t >> 5] = s2;
    __syncthreads();
    if (t == 0) {
        float tot = 0.f;
#pragma unroll
        for (int i = 0; i < 8; i++) tot += red[i];
        rstd_s = rsqrtf(tot * (1.f / EE) + 1e-5f);
    }
    __syncthreads();
    float val = (x - mu) * rstd_s * gam[t] + bet[t];
    out[base + t] = val;
    if (hout) hout[base + t] = __float2half_rn(val);
    if (hq)   hq[base + t]   = __float2half_rn(val + qpos[base + t]);
}

// ---------------- attention-weight softmax over 16 (stride-384 rows) -------
__global__ void awsm_kernel(float* __restrict__ offaw) {
    int i = blockIdx.x * blockDim.x + threadIdx.x;
    if (i >= BB * QQ * NHH) return;
    float* p = offaw + (size_t)(i >> 3) * 384 + 256 + (i & 7) * 16;
    float v[16];
    float m = -1e30f;
#pragma unroll
    for (int j = 0; j < 16; j++) { v[j] = p[j]; m = fmaxf(m, v[j]); }
    float s = 0.f;
#pragma unroll
    for (int j = 0; j < 16; j++) { v[j] = __expf(v[j] - m); s += v[j]; }
    float inv = 1.f / s;
#pragma unroll
    for (int j = 0; j < 16; j++) p[j] = v[j] * inv;
}

// ---------------- deformable bilinear sampling (fp16 value) ----------------
__device__ __forceinline__ float fetch_corner_h(const __half* __restrict__ vb,
                                                float yi, float xi, int Hl, int Wl) {
    bool valid = (xi >= 0.f) && (xi <= (float)(Wl - 1)) &&
                 (yi >= 0.f) && (yi <= (float)(Hl - 1));
    int xc = (int)fminf(fmaxf(xi, 0.f), (float)(Wl - 1));
    int yc = (int)fminf(fmaxf(yi, 0.f), (float)(Hl - 1));
    float v = __half2float(vb[(size_t)(yc * Wl + xc) * EE]);
    return valid ? v : 0.f;
}

__global__ void sample_kernel(const float* __restrict__ refp, const float* __restrict__ offaw,
                              const __half* __restrict__ val, __half* __restrict__ out) {
    int wg = (blockIdx.x * blockDim.x + threadIdx.x) >> 5;
    int lane = threadIdx.x & 31;
    if (wg >= BB * QQ * NHH) return;
    int h = wg % NHH;
    int bq = wg / NHH;
    int b = bq / QQ;

    const float* rp = refp + (size_t)bq * 8;
    const float* op = offaw + (size_t)bq * 384 + h * 32;
    const float* ap = offaw + (size_t)bq * 384 + 256 + h * 16;

    const int Hs[4] = {128, 64, 32, 16};
    const int S0[4] = {0, 16384, 20480, 21504};

    float acc = 0.f;
#pragma unroll
    for (int l = 0; l < 4; l++) {
        int Hi = Hs[l], Wi = Hs[l];
        float Hl = (float)Hi, Wl = (float)Wi;
        const __half* vb = val + ((size_t)b * STOT + S0[l]) * EE + h * 32 + lane;
        float rx = rp[l * 2 + 0], ry = rp[l * 2 + 1];
#pragma unroll
        for (int p = 0; p < 4; p++) {
            float ox = op[l * 8 + p * 2 + 0];
            float oy = op[l * 8 + p * 2 + 1];
            float a = ap[l * 4 + p];
            float x = fmaf(rx, Wl, ox) - 0.5f;
            float y = fmaf(ry, Hl, oy) - 0.5f;
            float x0 = floorf(x), y0 = floorf(y);
            float wx = x - x0, wy = y - y0;
            float sum = 0.f;
            sum += fetch_corner_h(vb, y0,       x0,       Hi, Wi) * (1.f - wy) * (1.f - wx);
            sum += fetch_corner_h(vb, y0,       x0 + 1.f, Hi, Wi) * (1.f - wy) * wx;
            sum += fetch_corner_h(vb, y0 + 1.f, x0,       Hi, Wi) * wy * (1.f - wx);
            sum += fetch_corner_h(vb, y0 + 1.f, x0 + 1.f, Hi, Wi) * wy * wx;
            acc = fmaf(a, sum, acc);
        }
    }
    out[(size_t)bq * EE + h * 32 + lane] = __float2half_rn(acc);
}

// ---------------- launch ----------------
extern "C" void kernel_launch(void* const* d_in, const int* in_sizes, int n_in,
                              void* d_out, int out_size) {
    const float* tgt   = (const float*)d_in[0];
    const float* qpos  = (const float*)d_in[1];
    const float* refp  = (const float*)d_in[2];
    const float* src   = (const float*)d_in[3];
    const float* ipw   = (const float*)d_in[6];
    const float* ipb   = (const float*)d_in[7];
    const float* outpw = (const float*)d_in[8];
    const float* outpb = (const float*)d_in[9];
    const float* n1g   = (const float*)d_in[10];
    const float* n1b   = (const float*)d_in[11];
    const float* offb  = (const float*)d_in[13];
    const float* offw  = (const float*)d_in[12];
    const float* aww   = (const float*)d_in[14];
    const float* awb   = (const float*)d_in[15];
    const float* vpw   = (const float*)d_in[16];
    const float* vpb   = (const float*)d_in[17];
    const float* opw   = (const float*)d_in[18];
    const float* opb   = (const float*)d_in[19];
    const float* n2g   = (const float*)d_in[20];
    const float* n2b   = (const float*)d_in[21];
    const float* w1    = (const float*)d_in[22];
    const float* b1    = (const float*)d_in[23];
    const float* w2    = (const float*)d_in[24];
    const float* b2    = (const float*)d_in[25];
    const float* n3g   = (const float*)d_in[26];
    const float* n3b   = (const float*)d_in[27];
    float* out = (float*)d_out;

    float *tmp, *tgt1, *tgt2, *offaw, *bias2;
    cudaGetSymbolAddress((void**)&tmp,   g_tmp);
    cudaGetSymbolAddress((void**)&tgt1,  g_tgt1);
    cudaGetSymbolAddress((void**)&tgt2,  g_tgt2);
    cudaGetSymbolAddress((void**)&offaw, g_offaw);
    cudaGetSymbolAddress((void**)&bias2, g_bias2);

    __half *hval, *hsrc, *htgt, *hipw, *houtpw, *hoffaw, *hvpw, *hopw, *hw1, *hw2;
    __half *hqk, *hqk2, *hv, *hctx, *hquery, *hsamp, *htgt2, *hffn1;
    cudaGetSymbolAddress((void**)&hval,   h_value);
    cudaGetSymbolAddress((void**)&hsrc,   h_src);
    cudaGetSymbolAddress((void**)&htgt,   h_tgt);
    cudaGetSymbolAddress((void**)&hipw,   h_ipw);
    cudaGetSymbolAddress((void**)&houtpw, h_outpw);
    cudaGetSymbolAddress((void**)&hoffaw, h_offaw);
    cudaGetSymbolAddress((void**)&hvpw,   h_vpw);
    cudaGetSymbolAddress((void**)&hopw,   h_opw);
    cudaGetSymbolAddress((void**)&hw1,    h_w1);
    cudaGetSymbolAddress((void**)&hw2,    h_w2);
    cudaGetSymbolAddress((void**)&hqk,    h_qk);
    cudaGetSymbolAddress((void**)&hqk2,   h_qk2);
    cudaGetSymbolAddress((void**)&hv,     h_v);
    cudaGetSymbolAddress((void**)&hctx,   h_ctx);
    cudaGetSymbolAddress((void**)&hquery, h_query);
    cudaGetSymbolAddress((void**)&hsamp,  h_samp);
    cudaGetSymbolAddress((void**)&htgt2,  h_tgt2);
    cudaGetSymbolAddress((void**)&hffn1,  h_ffn1);

    cudaFuncSetAttribute(gemm_h<0,0,1>, cudaFuncAttributeMaxDynamicSharedMemorySize, GEMMH_SMEM);
    cudaFuncSetAttribute(gemm_h<0,1,0>, cudaFuncAttributeMaxDynamicSharedMemorySize, GEMMH_SMEM);
    cudaFuncSetAttribute(gemm_h<1,0,1>, cudaFuncAttributeMaxDynamicSharedMemorySize, GEMMH_SMEM);
    cudaFuncSetAttribute(attn_h, cudaFuncAttributeMaxDynamicSharedMemorySize, ATT_SMEM_BYTES);

    // 0) bulk convert inputs/weights to fp16
    CvtArgs ca;
    const float* ss[10] = { tgt, src, ipw, outpw, offw, aww, vpw, opw, w1, w2 };
    __half* dd[10] = { htgt, hsrc, hipw, houtpw, hoffaw, hoffaw + 256*256, hvpw, hopw, hw1, hw2 };
    int nn[10] = { MM*EE/8, (int)((size_t)BB*STOT*EE/8), 768*256/8, 65536/8, 65536/8,
                   32768/8, 65536/8, 65536/8, 262144/8, 262144/8 };
    int total8 = 0;
    for (int i = 0; i < 10; i++) { ca.s[i] = ss[i]; ca.d[i] = dd[i]; ca.n8[i] = nn[i]; total8 += nn[i]; }
    cvt_kernel<<<(total8 + 255) / 256, 256>>>(ca, total8);
    pack_bias<<<1, 384>>>(offb, awb, bias2);

    const int M = MM;
    const int n4 = M * EE / 4;

    // 1) qk = tgt + query_pos (fp16)
    add_h<<<(n4 + 255) / 256, 256>>>((const float4*)tgt, (const float4*)qpos, hqk, n4);

    // 2) q|k merged projection + v projection
    gemm_h<0,0,1><<<dim3(4, M/128), 256, GEMMH_SMEM>>>(hqk, hipw,           ipb,     nullptr, hqk2, M, 512, 256);
    gemm_h<0,0,1><<<dim3(2, M/128), 256, GEMMH_SMEM>>>(htgt, hipw + 512*256, ipb+512, nullptr, hv,   M, 256, 256);

    // 3) self-attention
    attn_h<<<dim3(QQ/128, BB*NHH), 256, ATT_SMEM_BYTES>>>(hqk2, 512, hqk2 + 256, 512, hv, 256, hctx);

    // 4) out projection + LN1 (fused query = LN1 + qpos, fp16)
    gemm_h<0,1,0><<<dim3(2, M/128), 256, GEMMH_SMEM>>>(hctx, houtpw, outpb, tmp, nullptr, M, 256, 256);
    addln_kernel<<<M, 256>>>(tgt, tmp, n1g, n1b, tgt1, nullptr, qpos, hquery);

    // 5) value projection -> fp16 value
    gemm_h<0,0,1><<<dim3(2, (BB*STOT)/128), 256, GEMMH_SMEM>>>(hsrc, hvpw, vpb, nullptr, hval, BB*STOT, 256, 256);

    // 6) merged offsets|attention-weights projection (N=384)
    gemm_h<0,1,0><<<dim3(3, M/128), 256, GEMMH_SMEM>>>(hquery, hoffaw, bias2, offaw, nullptr, M, 384, 256);
    awsm_kernel<<<(BB*QQ*NHH + 255) / 256, 256>>>(offaw);

    // 7) deformable sampling (fp16 value, fp16 out)
    sample_kernel<<<(BB*QQ*NHH) / 8, 256>>>(refp, offaw, hval, hsamp);

    // 8) output projection + LN2
    gemm_h<0,1,0><<<dim3(2, M/128), 256, GEMMH_SMEM>>>(hsamp, hopw, opb, tmp, nullptr, M, 256, 256);
    addln_kernel<<<M, 256>>>(tgt1, tmp, n2g, n2b, tgt2, htgt2, nullptr, nullptr);

    // 9) FFN + LN3
    gemm_h<1,0,1><<<dim3(8, M/128), 256, GEMMH_SMEM>>>(htgt2, hw1, b1, nullptr, hffn1, M, 1024, 256);
    gemm_h<0,1,0><<<dim3(2, M/128), 256, GEMMH_SMEM>>>(hffn1, hw2, b2, tmp, nullptr, M, 256, 1024);
    addln_kernel<<<M, 256>>>(tgt2, tmp, n3g, n3b, out, nullptr, nullptr, nullptr);
}

// round 10
// speedup vs baseline: 1.0469x; 1.0127x over previous
#include <cuda_runtime.h>
#include <cuda_fp16.h>
#include <math.h>
#include <stdint.h>

#define BB   8
#define QQ   1024
#define EE   256
#define NHH  8
#define DHH  32
#define STOT 21760
#define MM   (BB*QQ)

// ---------------- scratch (device globals: allocation-free) ----------------
__device__ float g_tmp  [MM*EE];
__device__ float g_tgt1 [MM*EE];
__device__ float g_tgt2 [MM*EE];
__device__ float g_offaw[MM*384];
__device__ float g_bias2[384];

__device__ __half h_value[(size_t)BB*STOT*EE];
__device__ __half h_src  [(size_t)BB*STOT*EE];
__device__ __half h_tgt  [MM*EE];
__device__ __half h_ipw  [768*256];
__device__ __half h_outpw[256*256];
__device__ __half h_offaw[384*256];
__device__ __half h_vpw  [256*256];
__device__ __half h_opw  [256*256];
__device__ __half h_w1   [1024*256];
__device__ __half h_w2   [256*1024];
__device__ __half h_qk   [MM*EE];
__device__ __half h_qk2  [MM*512];
__device__ __half h_v    [MM*EE];
__device__ __half h_ctx  [MM*EE];
__device__ __half h_query[MM*EE];
__device__ __half h_samp [MM*EE];
__device__ __half h_tgt2 [MM*EE];
__device__ __half h_ffn1 [MM*1024];

// ---------------- helpers ----------------
__device__ __forceinline__ void mma_f16(float* c,
                                        uint32_t a0, uint32_t a1, uint32_t a2, uint32_t a3,
                                        uint32_t b0, uint32_t b1) {
    asm volatile("mma.sync.aligned.m16n8k16.row.col.f32.f16.f16.f32 "
                 "{%0,%1,%2,%3}, {%4,%5,%6,%7}, {%8,%9}, {%0,%1,%2,%3};\n"
                 : "+f"(c[0]), "+f"(c[1]), "+f"(c[2]), "+f"(c[3])
                 : "r"(a0), "r"(a1), "r"(a2), "r"(a3), "r"(b0), "r"(b1));
}

__device__ __forceinline__ void ldsm_x4(uint32_t* r, uint32_t addr) {
    asm volatile("ldmatrix.sync.aligned.m8n8.x4.shared.b16 {%0,%1,%2,%3}, [%4];\n"
                 : "=r"(r[0]), "=r"(r[1]), "=r"(r[2]), "=r"(r[3]) : "r"(addr));
}

__device__ __forceinline__ void cp_async16(uint32_t smem_addr, const void* gmem) {
    asm volatile("cp.async.ca.shared.global [%0], [%1], 16;\n" :: "r"(smem_addr), "l"(gmem));
}

__device__ __forceinline__ uint32_t packh2(float a, float b) {
    __half2 h = __floats2half2_rn(a, b);
    return *(uint32_t*)&h;
}

// ---------------- bulk fp32 -> fp16 convert (<=10 segments) ----------------
struct CvtArgs {
    const float* s[10];
    __half* d[10];
    int n8[10];
};
__global__ void cvt_kernel(CvtArgs a, int total8) {
    int i = blockIdx.x * blockDim.x + threadIdx.x;
    if (i >= total8) return;
    int seg = 0;
#pragma unroll
    for (int k = 0; k < 10; k++) {
        if (i >= a.n8[seg]) { i -= a.n8[seg]; seg++; } else break;
    }
    const float4* sp = (const float4*)a.s[seg] + (size_t)i * 2;
    float4 x = sp[0], y = sp[1];
    uint4 o;
    o.x = packh2(x.x, x.y); o.y = packh2(x.z, x.w);
    o.z = packh2(y.x, y.y); o.w = packh2(y.z, y.w);
    ((uint4*)a.d[seg])[i] = o;
}

__global__ void pack_bias(const float* __restrict__ offb, const float* __restrict__ awb,
                          float* __restrict__ dst) {
    int t = threadIdx.x;
    if (t < 256) dst[t] = offb[t];
    else if (t < 384) dst[t] = awb[t - 256];
}

// ---------------- add (f32 + f32 -> f16) ----------------
__global__ void add_h(const float4* __restrict__ a, const float4* __restrict__ b,
                      __half* __restrict__ c, int n4) {
    int i = blockIdx.x * blockDim.x + threadIdx.x;
    if (i >= n4) return;
    float4 x = a[i], y = b[i];
    uint2 o;
    o.x = packh2(x.x + y.x, x.y + y.y);
    o.y = packh2(x.z + y.z, x.w + y.w);
    ((uint2*)c)[i] = o;
}

// ---------------- fp16 tensor-core GEMM ----------------
#define HSMS 72
#define HSTG (128 * HSMS)
template<int RELU, int WF32, int WF16>
__global__ __launch_bounds__(256, 2)
void gemm_h(const __half* __restrict__ A, const __half* __restrict__ W,
            const float* __restrict__ bias, float* __restrict__ C,
            __half* __restrict__ Ch, int M, int N, int K) {
    extern __shared__ __half smh[];
    const uint32_t base = (uint32_t)__cvta_generic_to_shared(smh);
    uint32_t AsmA[2] = { base,               base + HSTG * 2 };
    uint32_t WsmA[2] = { base + 2*HSTG*2,    base + 3*HSTG*2 };

    const int bm = blockIdx.y * 128;
    const int bn = blockIdx.x * 128;
    const int tid  = threadIdx.x;
    const int warp = tid >> 5;
    const int lane = tid & 31;
    const int wm = warp >> 1;
    const int wn = warp & 1;
    const int lr = lane >> 2;
    const int lc = lane & 3;
    const int l16 = lane & 15;
    const int l4  = lane >> 4;

    uint32_t aOff[2], bOff[4];
#pragma unroll
    for (int mi = 0; mi < 2; mi++)
        aOff[mi] = (wm * 32 + mi * 16 + l16) * (HSMS * 2) + l4 * 16;
#pragma unroll
    for (int p = 0; p < 4; p++)
        bOff[p] = (wn * 64 + p * 16 + l16) * (HSMS * 2) + l4 * 16;

    float acc[2][8][4];
#pragma unroll
    for (int mi = 0; mi < 2; mi++)
#pragma unroll
        for (int ni = 0; ni < 8; ni++)
#pragma unroll
            for (int t = 0; t < 4; t++) acc[mi][ni][t] = 0.f;

    const int lrow = tid >> 1;
    const int lseg = tid & 1;
    const __half* Ag = A + (size_t)(bm + lrow) * K + lseg * 32;
    const __half* Wg = W + (size_t)(bn + lrow) * K + lseg * 32;
    uint32_t aSt[2], wSt[2];
#pragma unroll
    for (int s = 0; s < 2; s++) {
        aSt[s] = AsmA[s] + lrow * (HSMS * 2) + lseg * 64;
        wSt[s] = WsmA[s] + lrow * (HSMS * 2) + lseg * 64;
    }

    const int nch = K >> 6;

#pragma unroll
    for (int j = 0; j < 4; j++) {
        cp_async16(aSt[0] + j * 16, Ag + j * 8);
        cp_async16(wSt[0] + j * 16, Wg + j * 8);
    }
    asm volatile("cp.async.commit_group;\n");

    for (int c = 0; c < nch; c++) {
        const int cur = c & 1;
        if (c + 1 < nch) {
            const __half* Agn = Ag + (size_t)(c + 1) * 64;
            const __half* Wgn = Wg + (size_t)(c + 1) * 64;
            const int nxt = cur ^ 1;
#pragma unroll
            for (int j = 0; j < 4; j++) {
                cp_async16(aSt[nxt] + j * 16, Agn + j * 8);
                cp_async16(wSt[nxt] + j * 16, Wgn + j * 8);
            }
            asm volatile("cp.async.commit_group;\n");
            asm volatile("cp.async.wait_group 1;\n");
        } else {
            asm volatile("cp.async.wait_group 0;\n");
        }
        __syncthreads();

        const uint32_t aS = AsmA[cur];
        const uint32_t wS = WsmA[cur];
#pragma unroll
        for (int kk = 0; kk < 4; kk++) {
            uint32_t a0[4], a1[4];
            ldsm_x4(a0, aS + aOff[0] + kk * 32);
            ldsm_x4(a1, aS + aOff[1] + kk * 32);
#pragma unroll
            for (int p = 0; p < 4; p++) {
                uint32_t bf[4];
                ldsm_x4(bf, wS + bOff[p] + kk * 32);
                mma_f16(acc[0][2*p],   a0[0], a0[1], a0[2], a0[3], bf[0], bf[2]);
                mma_f16(acc[1][2*p],   a1[0], a1[1], a1[2], a1[3], bf[0], bf[2]);
                mma_f16(acc[0][2*p+1], a0[0], a0[1], a0[2], a0[3], bf[1], bf[3]);
                mma_f16(acc[1][2*p+1], a1[0], a1[1], a1[2], a1[3], bf[1], bf[3]);
            }
        }
        __syncthreads();
    }

#pragma unroll
    for (int ni = 0; ni < 8; ni++) {
        int col = bn + wn * 64 + ni * 8 + lc * 2;
        float bj0 = bias[col], bj1 = bias[col + 1];
#pragma unroll
        for (int mi = 0; mi < 2; mi++) {
            int row = bm + wm * 32 + mi * 16 + lr;
            float v0 = acc[mi][ni][0] + bj0;
            float v1 = acc[mi][ni][1] + bj1;
            float v2 = acc[mi][ni][2] + bj0;
            float v3 = acc[mi][ni][3] + bj1;
            if (RELU) {
                v0 = fmaxf(v0, 0.f); v1 = fmaxf(v1, 0.f);
                v2 = fmaxf(v2, 0.f); v3 = fmaxf(v3, 0.f);
            }
            if (WF32) {
                *(float2*)(C + (size_t)row * N + col)       = make_float2(v0, v1);
                *(float2*)(C + (size_t)(row + 8) * N + col) = make_float2(v2, v3);
            }
            if (WF16) {
                *(uint32_t*)(Ch + (size_t)row * N + col)       = packh2(v0, v1);
                *(uint32_t*)(Ch + (size_t)(row + 8) * N + col) = packh2(v2, v3);
            }
        }
    }
}
#define GEMMH_SMEM (4 * HSTG * 2)

// ---------------- fp16 tensor-core self-attention ----------------
#define AQ_OFF  0
#define AK0_OFF 5120
#define AK1_OFF 7680
#define AV_OFF  10240
#define AP_OFF  12544
#define ATT_SMEM_BYTES ((12544 + 9216) * 2)

__global__ __launch_bounds__(256, 2)
void attn_h(const __half* __restrict__ Qm, int ldq,
            const __half* __restrict__ Km, int ldk,
            const __half* __restrict__ Vm, int ldv,
            __half* __restrict__ Om) {
    extern __shared__ __half sh[];
    const uint32_t shA = (uint32_t)__cvta_generic_to_shared(sh);
    const uint32_t qA  = shA + AQ_OFF * 2;
    uint32_t ksA[2] = { shA + AK0_OFF * 2, shA + AK1_OFF * 2 };
    const uint32_t vtA = shA + AV_OFF * 2;
    const uint32_t pA  = shA + AP_OFF * 2;
    __half* Vts = sh + AV_OFF;
    __half* Ps  = sh + AP_OFF;

    const int bh = blockIdx.y;
    const int b = bh / NHH, h = bh % NHH;
    const int q0 = blockIdx.x * 128;
    const int tid = threadIdx.x;
    const int warp = tid >> 5;
    const int lane = tid & 31;
    const int lr = lane >> 2;
    const int lc = lane & 3;
    const int l16 = lane & 15;
    const int l4  = lane >> 4;
    const int m0 = warp * 16;
    const float scale = 0.17677669529663687f;

    {
        const int lrow = tid >> 1, lseg = tid & 1;
        const __half* qp = Qm + (size_t)(b * QQ + q0 + lrow) * ldq + h * DHH + lseg * 16;
        uint32_t dst = qA + lrow * 80 + lseg * 32;
        cp_async16(dst, qp);
        cp_async16(dst + 16, qp + 8);
    }
    const int krow = tid >> 2;
    const int kseg = tid & 3;
    const __half* kgBase = Km + (size_t)(b * QQ + krow) * ldk + h * DHH + kseg * 8;
    const uint32_t kstOff = krow * 80 + kseg * 16;
    cp_async16(ksA[0] + kstOff, kgBase);
    asm volatile("cp.async.commit_group;\n");

    const int vc = tid & 3;
    const int vr = tid >> 2;
    const int vkc = vc * 8;
    const int vkr = (vr + 8 * vc) & 63;
    const __half* vgBase = Vm + (size_t)(b * QQ + vkr) * ldv + h * DHH + vkc;
    __half* vtDst = Vts + vkc * 72 + vkr;
    uint4 vReg = *(const uint4*)vgBase;

    asm volatile("cp.async.wait_group 0;\n");
    __syncthreads();

    uint32_t qf[2][4];
#pragma unroll
    for (int kb = 0; kb < 2; kb++)
        ldsm_x4(qf[kb], qA + (m0 + l16) * 80 + l4 * 16 + kb * 32);

    {
        const __half* vh = (const __half*)&vReg;
#pragma unroll
        for (int j = 0; j < 8; j++) vtDst[j * 72] = vh[j];
    }
    __syncthreads();

    float acc_o[4][4];
#pragma unroll
    for (int ni = 0; ni < 4; ni++)
#pragma unroll
        for (int t = 0; t < 4; t++) acc_o[ni][t] = 0.f;
    float rs0 = 0.f, rs1 = 0.f;

    const int NT = QQ / 64;
    for (int t = 0; t < NT; t++) {
        const int cur = t & 1;
        const bool more = (t + 1 < NT);
        if (more) {
            cp_async16(ksA[cur ^ 1] + kstOff, kgBase + (size_t)(t + 1) * 64 * ldk);
            asm volatile("cp.async.commit_group;\n");
            vReg = *(const uint4*)(vgBase + (size_t)(t + 1) * 64 * ldv);
        }

        float accs[8][4];
#pragma unroll
        for (int ni = 0; ni < 8; ni++)
#pragma unroll
            for (int tt = 0; tt < 4; tt++) accs[ni][tt] = 0.f;
#pragma unroll
        for (int kb = 0; kb < 2; kb++) {
#pragma unroll
            for (int p = 0; p < 4; p++) {
                uint32_t bf[4];
                ldsm_x4(bf, ksA[cur] + (p * 16 + l16) * 80 + l4 * 16 + kb * 32);
                mma_f16(accs[2*p],   qf[kb][0], qf[kb][1], qf[kb][2], qf[kb][3], bf[0], bf[2]);
                mma_f16(accs[2*p+1], qf[kb][0], qf[kb][1], qf[kb][2], qf[kb][3], bf[1], bf[3]);
            }
        }

#pragma unroll
        for (int ni = 0; ni < 8; ni++) {
            float p0 = __expf(accs[ni][0] * scale);
            float p1 = __expf(accs[ni][1] * scale);
            float p2 = __expf(accs[ni][2] * scale);
            float p3 = __expf(accs[ni][3] * scale);
            rs0 += p0 + p1;
            rs1 += p2 + p3;
            *(uint32_t*)(Ps + (m0 + lr) * 72 + ni * 8 + 2 * lc)     = packh2(p0, p1);
            *(uint32_t*)(Ps + (m0 + 8 + lr) * 72 + ni * 8 + 2 * lc) = packh2(p2, p3);
        }
        __syncwarp();

#pragma unroll
        for (int kb = 0; kb < 4; kb++) {
            uint32_t af[4];
            ldsm_x4(af, pA + (m0 + l16) * 144 + l4 * 16 + kb * 32);
#pragma unroll
            for (int p = 0; p < 2; p++) {
                uint32_t bf[4];
                ldsm_x4(bf, vtA + (p * 16 + l16) * 144 + l4 * 16 + kb * 32);
                mma_f16(acc_o[2*p],   af[0], af[1], af[2], af[3], bf[0], bf[2]);
                mma_f16(acc_o[2*p+1], af[0], af[1], af[2], af[3], bf[1], bf[3]);
            }
        }
        __syncthreads();

        if (more) {
            asm volatile("cp.async.wait_group 0;\n");
            const __half* vh = (const __half*)&vReg;
#pragma unroll
            for (int j = 0; j < 8; j++) vtDst[j * 72] = vh[j];
            __syncthreads();
        }
    }

    rs0 += __shfl_xor_sync(0xffffffff, rs0, 1);
    rs0 += __shfl_xor_sync(0xffffffff, rs0, 2);
    rs1 += __shfl_xor_sync(0xffffffff, rs1, 1);
    rs1 += __shfl_xor_sync(0xffffffff, rs1, 2);
    float inv0 = 1.f / rs0;
    float inv1 = 1.f / rs1;

#pragma unroll
    for (int ni = 0; ni < 4; ni++) {
        int col = h * DHH + ni * 8 + 2 * lc;
        size_t row0 = (size_t)(b * QQ + q0 + m0 + lr) * EE + col;
        size_t row1 = (size_t)(b * QQ + q0 + m0 + 8 + lr) * EE + col;
        *(uint32_t*)(Om + row0) = packh2(acc_o[ni][0] * inv0, acc_o[ni][1] * inv0);
        *(uint32_t*)(Om + row1) = packh2(acc_o[ni][2] * inv1, acc_o[ni][3] * inv1);
    }
}

// ---------------- residual add + LayerNorm (rows of 256) ----------------
__global__ void addln_kernel(const float* __restrict__ X, const float* __restrict__ Y,
                             const float* __restrict__ gam, const float* __restrict__ bet,
                             float* __restrict__ out, __half* __restrict__ hout,
                             const float* __restrict__ qpos, __half* __restrict__ hq) {
    int row = blockIdx.x;
    int t = threadIdx.x;
    size_t base = (size_t)row * EE;
    float x = X[base + t] + Y[base + t];

    __shared__ float red[8];
    __shared__ float mu_s, rstd_s;

    float s = x;
#pragma unroll
    for (int o = 16; o > 0; o >>= 1) s += __shfl_down_sync(0xffffffff, s, o);
    if ((t & 31) == 0) red[t >> 5] = s;
    __syncthreads();
    if (t == 0) {
        float tot = 0.f;
#pragma unroll
        for (int i = 0; i < 8; i++) tot += red[i];
        mu_s = tot * (1.f / EE);
    }
    __syncthreads();
    float mu = mu_s;
    float d = x - mu;
    float s2 = d * d;
#pragma unroll
    for (int o = 16; o > 0; o >>= 1) s2 += __shfl_down_sync(0xffffffff, s2, o);
    if ((t & 31) == 0) red[t >> 5] = s2;
    __syncthreads();
    if (t == 0) {
        float tot = 0.f;
#pragma unroll
        for (int i = 0; i < 8; i++) tot += red[i];
        rstd_s = rsqrtf(tot * (1.f / EE) + 1e-5f);
    }
    __syncthreads();
    float val = (x - mu) * rstd_s * gam[t] + bet[t];
    out[base + t] = val;
    if (hout) hout[base + t] = __float2half_rn(val);
    if (hq)   hq[base + t]   = __float2half_rn(val + qpos[base + t]);
}

// ---------------- attention-weight softmax over 16 (stride-384 rows) -------
__global__ void awsm_kernel(float* __restrict__ offaw) {
    int i = blockIdx.x * blockDim.x + threadIdx.x;
    if (i >= BB * QQ * NHH) return;
    float* p = offaw + (size_t)(i >> 3) * 384 + 256 + (i & 7) * 16;
    float v[16];
    float m = -1e30f;
#pragma unroll
    for (int j = 0; j < 16; j++) { v[j] = p[j]; m = fmaxf(m, v[j]); }
    float s = 0.f;
#pragma unroll
    for (int j = 0; j < 16; j++) { v[j] = __expf(v[j] - m); s += v[j]; }
    float inv = 1.f / s;
#pragma unroll
    for (int j = 0; j < 16; j++) p[j] = v[j] * inv;
}

// ---------------- deformable bilinear sampling (fp16 value) ----------------
__device__ __forceinline__ float fetch_corner_h(const __half* __restrict__ vb,
                                                float yi, float xi, int Hl, int Wl) {
    bool valid = (xi >= 0.f) && (xi <= (float)(Wl - 1)) &&
                 (yi >= 0.f) && (yi <= (float)(Hl - 1));
    int xc = (int)fminf(fmaxf(xi, 0.f), (float)(Wl - 1));
    int yc = (int)fminf(fmaxf(yi, 0.f), (float)(Hl - 1));
    float v = __half2float(vb[(size_t)(yc * Wl + xc) * EE]);
    return valid ? v : 0.f;
}

__global__ void sample_kernel(const float* __restrict__ refp, const float* __restrict__ offaw,
                              const __half* __restrict__ val, __half* __restrict__ out) {
    int wg = (blockIdx.x * blockDim.x + threadIdx.x) >> 5;
    int lane = threadIdx.x & 31;
    if (wg >= BB * QQ * NHH) return;
    int h = wg % NHH;
    int bq = wg / NHH;
    int b = bq / QQ;

    const float* rp = refp + (size_t)bq * 8;
    const float* op = offaw + (size_t)bq * 384 + h * 32;
    const float* ap = offaw + (size_t)bq * 384 + 256 + h * 16;

    const int Hs[4] = {128, 64, 32, 16};
    const int S0[4] = {0, 16384, 20480, 21504};

    float acc = 0.f;
#pragma unroll
    for (int l = 0; l < 4; l++) {
        int Hi = Hs[l], Wi = Hs[l];
        float Hl = (float)Hi, Wl = (float)Wi;
        const __half* vb = val + ((size_t)b * STOT + S0[l]) * EE + h * 32 + lane;
        float rx = rp[l * 2 + 0], ry = rp[l * 2 + 1];
#pragma unroll
        for (int p = 0; p < 4; p++) {
            float ox = op[l * 8 + p * 2 + 0];
            float oy = op[l * 8 + p * 2 + 1];
            float a = ap[l * 4 + p];
            float x = fmaf(rx, Wl, ox) - 0.5f;
            float y = fmaf(ry, Hl, oy) - 0.5f;
            float x0 = floorf(x), y0 = floorf(y);
            float wx = x - x0, wy = y - y0;
            float sum = 0.f;
            sum += fetch_corner_h(vb, y0,       x0,       Hi, Wi) * (1.f - wy) * (1.f - wx);
            sum += fetch_corner_h(vb, y0,       x0 + 1.f, Hi, Wi) * (1.f - wy) * wx;
            sum += fetch_corner_h(vb, y0 + 1.f, x0,       Hi, Wi) * wy * (1.f - wx);
            sum += fetch_corner_h(vb, y0 + 1.f, x0 + 1.f, Hi, Wi) * wy * wx;
            acc = fmaf(a, sum, acc);
        }
    }
    out[(size_t)bq * EE + h * 32 + lane] = __float2half_rn(acc);
}

// ---------------- launch ----------------
extern "C" void kernel_launch(void* const* d_in, const int* in_sizes, int n_in,
                              void* d_out, int out_size) {
    const float* tgt   = (const float*)d_in[0];
    const float* qpos  = (const float*)d_in[1];
    const float* refp  = (const float*)d_in[2];
    const float* src   = (const float*)d_in[3];
    const float* ipw   = (const float*)d_in[6];
    const float* ipb   = (const float*)d_in[7];
    const float* outpw = (const float*)d_in[8];
    const float* outpb = (const float*)d_in[9];
    const float* n1g   = (const float*)d_in[10];
    const float* n1b   = (const float*)d_in[11];
    const float* offw  = (const float*)d_in[12];
    const float* offb  = (const float*)d_in[13];
    const float* aww   = (const float*)d_in[14];
    const float* awb   = (const float*)d_in[15];
    const float* vpw   = (const float*)d_in[16];
    const float* vpb   = (const float*)d_in[17];
    const float* opw   = (const float*)d_in[18];
    const float* opb   = (const float*)d_in[19];
    const float* n2g   = (const float*)d_in[20];
    const float* n2b   = (const float*)d_in[21];
    const float* w1    = (const float*)d_in[22];
    const float* b1    = (const float*)d_in[23];
    const float* w2    = (const float*)d_in[24];
    const float* b2    = (const float*)d_in[25];
    const float* n3g   = (const float*)d_in[26];
    const float* n3b   = (const float*)d_in[27];
    float* out = (float*)d_out;

    float *tmp, *tgt1, *tgt2, *offaw, *bias2;
    cudaGetSymbolAddress((void**)&tmp,   g_tmp);
    cudaGetSymbolAddress((void**)&tgt1,  g_tgt1);
    cudaGetSymbolAddress((void**)&tgt2,  g_tgt2);
    cudaGetSymbolAddress((void**)&offaw, g_offaw);
    cudaGetSymbolAddress((void**)&bias2, g_bias2);

    __half *hval, *hsrc, *htgt, *hipw, *houtpw, *hoffaw, *hvpw, *hopw, *hw1, *hw2;
    __half *hqk, *hqk2, *hv, *hctx, *hquery, *hsamp, *htgt2, *hffn1;
    cudaGetSymbolAddress((void**)&hval,   h_value);
    cudaGetSymbolAddress((void**)&hsrc,   h_src);
    cudaGetSymbolAddress((void**)&htgt,   h_tgt);
    cudaGetSymbolAddress((void**)&hipw,   h_ipw);
    cudaGetSymbolAddress((void**)&houtpw, h_outpw);
    cudaGetSymbolAddress((void**)&hoffaw, h_offaw);
    cudaGetSymbolAddress((void**)&hvpw,   h_vpw);
    cudaGetSymbolAddress((void**)&hopw,   h_opw);
    cudaGetSymbolAddress((void**)&hw1,    h_w1);
    cudaGetSymbolAddress((void**)&hw2,    h_w2);
    cudaGetSymbolAddress((void**)&hqk,    h_qk);
    cudaGetSymbolAddress((void**)&hqk2,   h_qk2);
    cudaGetSymbolAddress((void**)&hv,     h_v);
    cudaGetSymbolAddress((void**)&hctx,   h_ctx);
    cudaGetSymbolAddress((void**)&hquery, h_query);
    cudaGetSymbolAddress((void**)&hsamp,  h_samp);
    cudaGetSymbolAddress((void**)&htgt2,  h_tgt2);
    cudaGetSymbolAddress((void**)&hffn1,  h_ffn1);

    cudaFuncSetAttribute(gemm_h<0,0,1>, cudaFuncAttributeMaxDynamicSharedMemorySize, GEMMH_SMEM);
    cudaFuncSetAttribute(gemm_h<0,1,0>, cudaFuncAttributeMaxDynamicSharedMemorySize, GEMMH_SMEM);
    cudaFuncSetAttribute(gemm_h<1,0,1>, cudaFuncAttributeMaxDynamicSharedMemorySize, GEMMH_SMEM);
    cudaFuncSetAttribute(attn_h, cudaFuncAttributeMaxDynamicSharedMemorySize, ATT_SMEM_BYTES);

    // fork-join stream for the src-cvt + value-projection branch
    cudaStream_t s1;
    cudaEvent_t eFork, eJoin;
    cudaStreamCreateWithFlags(&s1, cudaStreamNonBlocking);
    cudaEventCreateWithFlags(&eFork, cudaEventDisableTiming);
    cudaEventCreateWithFlags(&eJoin, cudaEventDisableTiming);

    const int M = MM;
    const int n4 = M * EE / 4;

    // ---- fork ----
    cudaEventRecord(eFork, 0);
    cudaStreamWaitEvent(s1, eFork, 0);

    // ---- branch B (s1): src + vpw cvt, then value projection ----
    {
        CvtArgs cb = {};
        cb.s[0] = src;  cb.d[0] = hsrc;  cb.n8[0] = (int)((size_t)BB*STOT*EE/8);
        cb.s[1] = vpw;  cb.d[1] = hvpw;  cb.n8[1] = 65536/8;
        for (int i = 2; i < 10; i++) { cb.s[i] = src; cb.d[i] = hsrc; cb.n8[i] = 0; }
        int totB = cb.n8[0] + cb.n8[1];
        cvt_kernel<<<(totB + 255) / 256, 256, 0, s1>>>(cb, totB);
        gemm_h<0,0,1><<<dim3(2, (BB*STOT)/128), 256, GEMMH_SMEM, s1>>>(hsrc, hvpw, vpb, nullptr, hval, BB*STOT, 256, 256);
        cudaEventRecord(eJoin, s1);
    }

    // ---- branch A (stream 0): weights cvt + attn chain ----
    {
        CvtArgs ca = {};
        const float* ss[8] = { tgt, ipw, outpw, offw, aww, opw, w1, w2 };
        __half* dd[8] = { htgt, hipw, houtpw, hoffaw, hoffaw + 256*256, hopw, hw1, hw2 };
        int nn[8] = { MM*EE/8, 768*256/8, 65536/8, 65536/8, 32768/8, 65536/8, 262144/8, 262144/8 };
        int totA = 0;
        for (int i = 0; i < 8; i++) { ca.s[i] = ss[i]; ca.d[i] = dd[i]; ca.n8[i] = nn[i]; totA += nn[i]; }
        for (int i = 8; i < 10; i++) { ca.s[i] = tgt; ca.d[i] = htgt; ca.n8[i] = 0; }
        cvt_kernel<<<(totA + 255) / 256, 256>>>(ca, totA);
    }
    pack_bias<<<1, 384>>>(offb, awb, bias2);

    add_h<<<(n4 + 255) / 256, 256>>>((const float4*)tgt, (const float4*)qpos, hqk, n4);
    gemm_h<0,0,1><<<dim3(4, M/128), 256, GEMMH_SMEM>>>(hqk, hipw,            ipb,     nullptr, hqk2, M, 512, 256);
    gemm_h<0,0,1><<<dim3(2, M/128), 256, GEMMH_SMEM>>>(htgt, hipw + 512*256, ipb+512, nullptr, hv,   M, 256, 256);
    attn_h<<<dim3(QQ/128, BB*NHH), 256, ATT_SMEM_BYTES>>>(hqk2, 512, hqk2 + 256, 512, hv, 256, hctx);
    gemm_h<0,1,0><<<dim3(2, M/128), 256, GEMMH_SMEM>>>(hctx, houtpw, outpb, tmp, nullptr, M, 256, 256);
    addln_kernel<<<M, 256>>>(tgt, tmp, n1g, n1b, tgt1, nullptr, qpos, hquery);
    gemm_h<0,1,0><<<dim3(3, M/128), 256, GEMMH_SMEM>>>(hquery, hoffaw, bias2, offaw, nullptr, M, 384, 256);
    awsm_kernel<<<(BB*QQ*NHH + 255) / 256, 256>>>(offaw);

    // ---- join: sample needs hval (branch B) + offaw (branch A) ----
    cudaStreamWaitEvent(0, eJoin, 0);
    sample_kernel<<<(BB*QQ*NHH) / 8, 256>>>(refp, offaw, hval, hsamp);

    gemm_h<0,1,0><<<dim3(2, M/128), 256, GEMMH_SMEM>>>(hsamp, hopw, opb, tmp, nullptr, M, 256, 256);
    addln_kernel<<<M, 256>>>(tgt1, tmp, n2g, n2b, tgt2, htgt2, nullptr, nullptr);

    gemm_h<1,0,1><<<dim3(8, M/128), 256, GEMMH_SMEM>>>(htgt2, hw1, b1, nullptr, hffn1, M, 1024, 256);
    gemm_h<0,1,0><<<dim3(2, M/128), 256, GEMMH_SMEM>>>(hffn1, hw2, b2, tmp, nullptr, M, 256, 1024);
    addln_kernel<<<M, 256>>>(tgt2, tmp, n3g, n3b, out, nullptr, nullptr, nullptr);
}